// round 1
// baseline (speedup 1.0000x reference)
#include <cuda_runtime.h>
#include <cuda_bf16.h>
#include <math.h>
#include <stdint.h>

#define MROWS 196608
#define DM 512
#define SEQL 48

// ---------------- device scratch (no allocations allowed) ----------------
__device__ __nv_bfloat16 g_wnt[512 * 512];
__device__ __nv_bfloat16 g_we1[1024 * 512];
__device__ __nv_bfloat16 g_we2[512 * 512];
__device__ __nv_bfloat16 g_wo[512 * 512];
__device__ __nv_bfloat16 g_wg[1024 * 512];
__device__ __nv_bfloat16 g_xt[(size_t)MROWS * DM];   // gelu(LN(x@Wnt))
__device__ __nv_bfloat16 g_wt[(size_t)MROWS * DM];   // adj-weighted x_t
__device__ __nv_bfloat16 g_h1[(size_t)MROWS * DM];   // gelu(edge_in@We1)
__device__ __nv_bfloat16 g_msg[(size_t)MROWS * DM];  // messages
__device__ float g_f32a[(size_t)MROWS * DM];         // h, then gate logits
__device__ float g_f32b[(size_t)MROWS * DM];         // messages@Wo + bo
__device__ float g_adj[SEQL * SEQL];                 // masked_adj
__device__ int g_hasnb[SEQL];

__device__ __forceinline__ float geluf(float x) {
    return 0.5f * x * (1.0f + erff(x * 0.7071067811865476f));
}

// ---------------- tiny kernels ----------------
__global__ void k_cvt(const float* __restrict__ s, __nv_bfloat16* __restrict__ d, int n) {
    int i = blockIdx.x * blockDim.x + threadIdx.x;
    int stride = gridDim.x * blockDim.x;
    for (; i < n; i += stride) d[i] = __float2bfloat16(s[i]);
}

__global__ void k_adj(const float* __restrict__ lw) {
    int i = threadIdx.x;
    if (i >= SEQL) return;
    float v[SEQL];
    float mx = -1e30f;
    #pragma unroll
    for (int j = 0; j < SEQL; j++) { v[j] = lw[i * SEQL + j]; mx = fmaxf(mx, v[j]); }
    float s = 0.f;
    #pragma unroll
    for (int j = 0; j < SEQL; j++) { v[j] = expf(v[j] - mx); s += v[j]; }
    float inv = 1.f / s;
    int any = 0;
    #pragma unroll
    for (int j = 0; j < SEQL; j++) {
        float a = v[j] * inv;
        int nb = (a > 0.01f);
        g_adj[i * SEQL + j] = nb ? a : 0.f;
        any |= nb;
    }
    g_hasnb[i] = any;
}

// ---------------- GEMM: C[M,512] = epi(A[M,KTOT] @ W[KTOT,512] + bias) ----------------
#define BMT 128
#define BNT 128
#define BKT 32
#define ASTR 40
#define BSTR 136

enum { EPI_F32 = 0, EPI_GELU = 1, EPI_MSG = 2 };

template <int KTOT, bool A0F32, bool CONCAT, int EPI>
__global__ void __launch_bounds__(256) gemm_k(
    const void* __restrict__ A0p, const __nv_bfloat16* __restrict__ A1,
    const __nv_bfloat16* __restrict__ W, const float* __restrict__ bias,
    void* __restrict__ outp)
{
    __shared__ __align__(16) __nv_bfloat16 As[2][BMT * ASTR];
    __shared__ __align__(16) __nv_bfloat16 Bs[2][BKT * BSTR];

    const int tid = threadIdx.x;
    const int lane = tid & 31;
    const int wid = tid >> 5;
    const int wm = wid >> 1;  // 0..3  -> 32 rows each
    const int wn = wid & 1;   // 0..1  -> 64 cols each
    const int bm = blockIdx.x;
    const int bn = blockIdx.y;

    float acc[2][8][4];
    #pragma unroll
    for (int i = 0; i < 2; i++)
        #pragma unroll
        for (int j = 0; j < 8; j++)
            #pragma unroll
            for (int k = 0; k < 4; k++) acc[i][j][k] = 0.f;

    uint4 rA[2], rB[2];

    auto ldA = [&](int kt) {
        #pragma unroll
        for (int i = 0; i < 2; i++) {
            int v = tid + (i << 8);
            int row = v >> 2;
            int k = (v & 3) << 3;
            long grow = (long)bm * BMT + row;
            int gk = kt * BKT + k;
            if (CONCAT && gk >= 512) {
                rA[i] = *reinterpret_cast<const uint4*>(A1 + grow * 512 + (gk - 512));
            } else if (A0F32) {
                const float* s = (const float*)A0p + grow * 512 + gk;
                float4 f0 = *reinterpret_cast<const float4*>(s);
                float4 f1 = *reinterpret_cast<const float4*>(s + 4);
                __nv_bfloat162 p0 = __floats2bfloat162_rn(f0.x, f0.y);
                __nv_bfloat162 p1 = __floats2bfloat162_rn(f0.z, f0.w);
                __nv_bfloat162 p2 = __floats2bfloat162_rn(f1.x, f1.y);
                __nv_bfloat162 p3 = __floats2bfloat162_rn(f1.z, f1.w);
                uint4 u;
                u.x = *reinterpret_cast<unsigned*>(&p0);
                u.y = *reinterpret_cast<unsigned*>(&p1);
                u.z = *reinterpret_cast<unsigned*>(&p2);
                u.w = *reinterpret_cast<unsigned*>(&p3);
                rA[i] = u;
            } else {
                rA[i] = *reinterpret_cast<const uint4*>((const __nv_bfloat16*)A0p + grow * 512 + gk);
            }
        }
    };
    auto stA = [&](int buf) {
        #pragma unroll
        for (int i = 0; i < 2; i++) {
            int v = tid + (i << 8);
            int row = v >> 2;
            int k = (v & 3) << 3;
            *reinterpret_cast<uint4*>(&As[buf][row * ASTR + k]) = rA[i];
        }
    };
    auto ldB = [&](int kt) {
        #pragma unroll
        for (int i = 0; i < 2; i++) {
            int v = tid + (i << 8);
            int kr = v >> 4;
            int n = (v & 15) << 3;
            rB[i] = *reinterpret_cast<const uint4*>(W + (long)(kt * BKT + kr) * 512 + bn * BNT + n);
        }
    };
    auto stB = [&](int buf) {
        #pragma unroll
        for (int i = 0; i < 2; i++) {
            int v = tid + (i << 8);
            int kr = v >> 4;
            int n = (v & 15) << 3;
            *reinterpret_cast<uint4*>(&Bs[buf][kr * BSTR + n]) = rB[i];
        }
    };

    auto compute = [&](int buf) {
        unsigned aBase = (unsigned)__cvta_generic_to_shared(&As[buf][0]);
        unsigned bBase = (unsigned)__cvta_generic_to_shared(&Bs[buf][0]);
        #pragma unroll
        for (int kk = 0; kk < BKT; kk += 16) {
            unsigned a[2][4];
            #pragma unroll
            for (int mi = 0; mi < 2; mi++) {
                int r = wm * 32 + mi * 16 + (lane & 15);
                int c = kk + ((lane >> 4) << 3);
                unsigned addr = aBase + (unsigned)((r * ASTR + c) * 2);
                asm volatile("ldmatrix.sync.aligned.m8n8.x4.shared.b16 {%0,%1,%2,%3}, [%4];\n"
                             : "=r"(a[mi][0]), "=r"(a[mi][1]), "=r"(a[mi][2]), "=r"(a[mi][3])
                             : "r"(addr));
            }
            unsigned b[4][4];
            #pragma unroll
            for (int bi = 0; bi < 4; bi++) {
                int r = kk + (lane & 15);
                int c = wn * 64 + bi * 16 + ((lane >> 4) << 3);
                unsigned addr = bBase + (unsigned)((r * BSTR + c) * 2);
                asm volatile("ldmatrix.sync.aligned.m8n8.x4.trans.shared.b16 {%0,%1,%2,%3}, [%4];\n"
                             : "=r"(b[bi][0]), "=r"(b[bi][1]), "=r"(b[bi][2]), "=r"(b[bi][3])
                             : "r"(addr));
            }
            #pragma unroll
            for (int mi = 0; mi < 2; mi++)
                #pragma unroll
                for (int ni = 0; ni < 8; ni++) {
                    unsigned b0 = b[ni >> 1][(ni & 1) * 2];
                    unsigned b1 = b[ni >> 1][(ni & 1) * 2 + 1];
                    asm volatile(
                        "mma.sync.aligned.m16n8k16.row.col.f32.bf16.bf16.f32 "
                        "{%0,%1,%2,%3}, {%4,%5,%6,%7}, {%8,%9}, {%0,%1,%2,%3};\n"
                        : "+f"(acc[mi][ni][0]), "+f"(acc[mi][ni][1]),
                          "+f"(acc[mi][ni][2]), "+f"(acc[mi][ni][3])
                        : "r"(a[mi][0]), "r"(a[mi][1]), "r"(a[mi][2]), "r"(a[mi][3]),
                          "r"(b0), "r"(b1));
                }
        }
    };

    const int nk = KTOT / BKT;
    ldA(0); ldB(0); stA(0); stB(0);
    __syncthreads();
    for (int kt = 0; kt < nk; kt++) {
        int cur = kt & 1;
        if (kt + 1 < nk) { ldA(kt + 1); ldB(kt + 1); }
        compute(cur);
        if (kt + 1 < nk) { stA(cur ^ 1); stB(cur ^ 1); }
        __syncthreads();
    }

    long rbase = (long)bm * BMT + wm * 32;
    int cbase = bn * BNT + wn * 64;
    #pragma unroll
    for (int mi = 0; mi < 2; mi++) {
        #pragma unroll
        for (int ni = 0; ni < 8; ni++) {
            int c0 = cbase + ni * 8 + (lane & 3) * 2;
            float bv0 = bias[c0], bv1 = bias[c0 + 1];
            long r0 = rbase + mi * 16 + (lane >> 2);
            long r1 = r0 + 8;
            float v00 = acc[mi][ni][0] + bv0;
            float v01 = acc[mi][ni][1] + bv1;
            float v10 = acc[mi][ni][2] + bv0;
            float v11 = acc[mi][ni][3] + bv1;
            if (EPI == EPI_F32) {
                float* o = (float*)outp;
                *reinterpret_cast<float2*>(o + r0 * 512 + c0) = make_float2(v00, v01);
                *reinterpret_cast<float2*>(o + r1 * 512 + c0) = make_float2(v10, v11);
            } else if (EPI == EPI_GELU) {
                __nv_bfloat16* o = (__nv_bfloat16*)outp;
                __nv_bfloat162 p0 = __floats2bfloat162_rn(geluf(v00), geluf(v01));
                __nv_bfloat162 p1 = __floats2bfloat162_rn(geluf(v10), geluf(v11));
                *reinterpret_cast<__nv_bfloat162*>(o + r0 * 512 + c0) = p0;
                *reinterpret_cast<__nv_bfloat162*>(o + r1 * 512 + c0) = p1;
            } else {  // EPI_MSG: messages = hasnb[s] ? msg : x_t
                __nv_bfloat16* o = (__nv_bfloat16*)outp;
                int s0 = (int)(r0 % SEQL), s1 = (int)(r1 % SEQL);
                if (!g_hasnb[s0]) {
                    v00 = __bfloat162float(g_xt[r0 * 512 + c0]);
                    v01 = __bfloat162float(g_xt[r0 * 512 + c0 + 1]);
                }
                if (!g_hasnb[s1]) {
                    v10 = __bfloat162float(g_xt[r1 * 512 + c0]);
                    v11 = __bfloat162float(g_xt[r1 * 512 + c0 + 1]);
                }
                __nv_bfloat162 p0 = __floats2bfloat162_rn(v00, v01);
                __nv_bfloat162 p1 = __floats2bfloat162_rn(v10, v11);
                *reinterpret_cast<__nv_bfloat162*>(o + r0 * 512 + c0) = p0;
                *reinterpret_cast<__nv_bfloat162*>(o + r1 * 512 + c0) = p1;
            }
        }
    }
}

// ---------------- LN + gelu (one warp per 512-wide row) ----------------
__global__ void __launch_bounds__(256) k_ln(const float* __restrict__ h,
                                            const float* __restrict__ lg,
                                            const float* __restrict__ lb) {
    long row = (long)blockIdx.x * 8 + (threadIdx.x >> 5);
    int lane = threadIdx.x & 31;
    const float* hr = h + row * 512;
    float v[16];
    float s = 0.f, s2 = 0.f;
    #pragma unroll
    for (int i = 0; i < 4; i++) {
        float4 f = *reinterpret_cast<const float4*>(hr + (i * 32 + lane) * 4);
        v[i * 4 + 0] = f.x; v[i * 4 + 1] = f.y; v[i * 4 + 2] = f.z; v[i * 4 + 3] = f.w;
        s += f.x + f.y + f.z + f.w;
        s2 += f.x * f.x + f.y * f.y + f.z * f.z + f.w * f.w;
    }
    #pragma unroll
    for (int o = 16; o > 0; o >>= 1) {
        s += __shfl_xor_sync(0xffffffffu, s, o);
        s2 += __shfl_xor_sync(0xffffffffu, s2, o);
    }
    float mu = s * (1.f / 512.f);
    float var = s2 * (1.f / 512.f) - mu * mu;
    float rstd = rsqrtf(var + 1e-5f);
    __nv_bfloat16* o = g_xt + row * 512;
    #pragma unroll
    for (int i = 0; i < 4; i++) {
        int c = (i * 32 + lane) * 4;
        float4 gv = *reinterpret_cast<const float4*>(lg + c);
        float4 bv = *reinterpret_cast<const float4*>(lb + c);
        float y0 = geluf((v[i * 4 + 0] - mu) * rstd * gv.x + bv.x);
        float y1 = geluf((v[i * 4 + 1] - mu) * rstd * gv.y + bv.y);
        float y2 = geluf((v[i * 4 + 2] - mu) * rstd * gv.z + bv.z);
        float y3 = geluf((v[i * 4 + 3] - mu) * rstd * gv.w + bv.w);
        __nv_bfloat162 p0 = __floats2bfloat162_rn(y0, y1);
        __nv_bfloat162 p1 = __floats2bfloat162_rn(y2, y3);
        uint2 u;
        u.x = *reinterpret_cast<unsigned*>(&p0);
        u.y = *reinterpret_cast<unsigned*>(&p1);
        *reinterpret_cast<uint2*>(o + c) = u;
    }
}

// ---------------- weighted = masked_adj @ x_t   (per batch, per 128-d chunk) ----------------
__global__ void __launch_bounds__(256) k_weighted() {
    int b = blockIdx.x;
    int dc = blockIdx.y;  // 0..3
    __shared__ float sadj[SEQL * SEQL];
    __shared__ __align__(16) __nv_bfloat16 sx[SEQL][128];
    int tid = threadIdx.x;
    for (int i = tid; i < SEQL * SEQL; i += 256) sadj[i] = g_adj[i];
    #pragma unroll
    for (int i = 0; i < 3; i++) {
        int v = tid + i * 256;
        int j = v >> 4;
        int n = (v & 15) << 3;
        *reinterpret_cast<uint4*>(&sx[j][n]) =
            *reinterpret_cast<const uint4*>(&g_xt[((long)b * SEQL + j) * 512 + dc * 128 + n]);
    }
    __syncthreads();
    int dd = tid & 127;
    int half = tid >> 7;
    float xcol[SEQL];
    #pragma unroll
    for (int j = 0; j < SEQL; j++) xcol[j] = __bfloat162float(sx[j][dd]);
    for (int ii = 0; ii < 24; ii++) {
        int i = half * 24 + ii;
        float a = 0.f;
        #pragma unroll
        for (int j = 0; j < SEQL; j++) a += sadj[i * SEQL + j] * xcol[j];
        g_wt[((long)b * SEQL + i) * 512 + dc * 128 + dd] = __float2bfloat16(a);
    }
}

// ---------------- final: out = sigmoid(gl)*mo + (1-sigmoid)*x ----------------
__global__ void __launch_bounds__(256) k_final(const float* __restrict__ x,
                                               float* __restrict__ out, long n4) {
    long i = (long)blockIdx.x * blockDim.x + threadIdx.x;
    long stride = (long)gridDim.x * blockDim.x;
    const float4* gl4 = reinterpret_cast<const float4*>(g_f32a);
    const float4* mo4 = reinterpret_cast<const float4*>(g_f32b);
    const float4* x4 = reinterpret_cast<const float4*>(x);
    float4* o4 = reinterpret_cast<float4*>(out);
    for (; i < n4; i += stride) {
        float4 gl = gl4[i];
        float4 mo = mo4[i];
        float4 xv = x4[i];
        float4 r;
        float sg;
        sg = 1.f / (1.f + expf(-gl.x)); r.x = sg * mo.x + (1.f - sg) * xv.x;
        sg = 1.f / (1.f + expf(-gl.y)); r.y = sg * mo.y + (1.f - sg) * xv.y;
        sg = 1.f / (1.f + expf(-gl.z)); r.z = sg * mo.z + (1.f - sg) * xv.z;
        sg = 1.f / (1.f + expf(-gl.w)); r.w = sg * mo.w + (1.f - sg) * xv.w;
        o4[i] = r;
    }
}

// ---------------- launch ----------------
extern "C" void kernel_launch(void* const* d_in, const int* in_sizes, int n_in,
                              void* d_out, int out_size) {
    const float* x = (const float*)d_in[0];
    const float* lw = (const float*)d_in[1];
    const float* Wnt = (const float*)d_in[2];
    const float* bnt = (const float*)d_in[3];
    const float* lng = (const float*)d_in[4];
    const float* lnb = (const float*)d_in[5];
    const float* We1 = (const float*)d_in[6];
    const float* be1 = (const float*)d_in[7];
    const float* We2 = (const float*)d_in[8];
    const float* be2 = (const float*)d_in[9];
    const float* Wo = (const float*)d_in[10];
    const float* bo = (const float*)d_in[11];
    const float* Wg = (const float*)d_in[12];
    const float* bg = (const float*)d_in[13];
    float* out = (float*)d_out;

    void *p_wnt, *p_we1, *p_we2, *p_wo, *p_wg, *p_xt, *p_wt, *p_h1, *p_msg, *p_a, *p_b;
    cudaGetSymbolAddress(&p_wnt, g_wnt);
    cudaGetSymbolAddress(&p_we1, g_we1);
    cudaGetSymbolAddress(&p_we2, g_we2);
    cudaGetSymbolAddress(&p_wo, g_wo);
    cudaGetSymbolAddress(&p_wg, g_wg);
    cudaGetSymbolAddress(&p_xt, g_xt);
    cudaGetSymbolAddress(&p_wt, g_wt);
    cudaGetSymbolAddress(&p_h1, g_h1);
    cudaGetSymbolAddress(&p_msg, g_msg);
    cudaGetSymbolAddress(&p_a, g_f32a);
    cudaGetSymbolAddress(&p_b, g_f32b);

    k_cvt<<<512, 256>>>(Wnt, (__nv_bfloat16*)p_wnt, 512 * 512);
    k_cvt<<<512, 256>>>(We1, (__nv_bfloat16*)p_we1, 1024 * 512);
    k_cvt<<<512, 256>>>(We2, (__nv_bfloat16*)p_we2, 512 * 512);
    k_cvt<<<512, 256>>>(Wo, (__nv_bfloat16*)p_wo, 512 * 512);
    k_cvt<<<512, 256>>>(Wg, (__nv_bfloat16*)p_wg, 1024 * 512);
    k_adj<<<1, 64>>>(lw);

    dim3 gg(MROWS / BMT, 512 / BNT);

    // h = x @ Wnt + bnt   (fp32 out)
    gemm_k<512, true, false, EPI_F32><<<gg, 256>>>(x, nullptr, (__nv_bfloat16*)p_wnt, bnt, p_a);
    // x_t = gelu(LN(h))
    k_ln<<<MROWS / 8, 256>>>((const float*)p_a, lng, lnb);
    // weighted = masked_adj @ x_t
    k_weighted<<<dim3(4096, 4), 256>>>();
    // h1 = gelu([x_t | weighted] @ We1 + be1)
    gemm_k<1024, false, true, EPI_GELU><<<gg, 256>>>(p_xt, (const __nv_bfloat16*)p_wt,
                                                     (__nv_bfloat16*)p_we1, be1, p_h1);
    // messages = blend(h1 @ We2 + be2, x_t)
    gemm_k<512, false, false, EPI_MSG><<<gg, 256>>>(p_h1, nullptr, (__nv_bfloat16*)p_we2, be2, p_msg);
    // gate logits = [x | messages] @ Wg + bg   (fp32 out)
    gemm_k<1024, true, true, EPI_F32><<<gg, 256>>>(x, (const __nv_bfloat16*)p_msg,
                                                   (__nv_bfloat16*)p_wg, bg, p_a);
    // mo = messages @ Wo + bo   (fp32 out)
    gemm_k<512, false, false, EPI_F32><<<gg, 256>>>(p_msg, nullptr, (__nv_bfloat16*)p_wo, bo, p_b);
    // out = sigmoid(gl)*mo + (1-sigmoid)*x
    k_final<<<24576, 256>>>(x, out, (long)MROWS * DM / 4);
}

// round 2
// speedup vs baseline: 1.1607x; 1.1607x over previous
#include <cuda_runtime.h>
#include <cuda_bf16.h>
#include <math.h>
#include <stdint.h>

#define MROWS 196608
#define SEQL 48

#define STAGES 3
#define ASTR 72
#define BSTR 136
#define A_ELEMS (128 * ASTR)
#define B_ELEMS (64 * BSTR)
#define SMEM_BYTES (STAGES * (A_ELEMS + B_ELEMS) * 2)

// ---------------- device scratch ----------------
__device__ __align__(128) __nv_bfloat16 g_wnt[512 * 512];
__device__ __align__(128) __nv_bfloat16 g_we1[1024 * 512];
__device__ __align__(128) __nv_bfloat16 g_we2[512 * 512];
__device__ __align__(128) __nv_bfloat16 g_wo[512 * 512];
__device__ __align__(128) __nv_bfloat16 g_wg[1024 * 512];
__device__ __align__(128) __nv_bfloat16 g_xbf[(size_t)MROWS * 512];  // x in bf16
__device__ __align__(128) __nv_bfloat16 g_xt[(size_t)MROWS * 512];   // gelu(LN(h))
__device__ __align__(128) __nv_bfloat16 g_wt[(size_t)MROWS * 512];   // adj-weighted x_t
__device__ __align__(128) __nv_bfloat16 g_h1[(size_t)MROWS * 512];   // gelu(edge@We1)
__device__ __align__(128) __nv_bfloat16 g_msg[(size_t)MROWS * 512];  // messages
__device__ __align__(128) float g_h[(size_t)MROWS * 512];            // h fp32 (pre-LN)
__device__ float g_adj[SEQL * SEQL];
__device__ int g_hasnb[SEQL];

__device__ __forceinline__ float geluf(float x) {
    return 0.5f * x * (1.0f + erff(x * 0.7071067811865476f));
}
__device__ __forceinline__ float sigf(float x) { return 1.f / (1.f + expf(-x)); }

__device__ __forceinline__ void cp16(unsigned dst, const void* src) {
    asm volatile("cp.async.cg.shared.global [%0], [%1], 16;\n" :: "r"(dst), "l"(src));
}

// ---------------- prep: convert x + all weights to bf16 (one launch) ----------------
__global__ void k_prep(const float* __restrict__ x, const float* __restrict__ Wnt,
                       const float* __restrict__ We1, const float* __restrict__ We2,
                       const float* __restrict__ Wo, const float* __restrict__ Wg) {
    const long Q0 = 25165824;  // x quads
    const long Q1 = 65536, Q2 = 131072, Q3 = 65536, Q4 = 65536, Q5 = 131072;
    const long QT = Q0 + Q1 + Q2 + Q3 + Q4 + Q5;
    for (long q = (long)blockIdx.x * blockDim.x + threadIdx.x; q < QT;
         q += (long)gridDim.x * blockDim.x) {
        const float* s; __nv_bfloat16* d; long o;
        if (q < Q0) { s = x; d = g_xbf; o = q; }
        else if (q < Q0 + Q1) { s = Wnt; d = g_wnt; o = q - Q0; }
        else if (q < Q0 + Q1 + Q2) { s = We1; d = g_we1; o = q - Q0 - Q1; }
        else if (q < Q0 + Q1 + Q2 + Q3) { s = We2; d = g_we2; o = q - Q0 - Q1 - Q2; }
        else if (q < Q0 + Q1 + Q2 + Q3 + Q4) { s = Wo; d = g_wo; o = q - Q0 - Q1 - Q2 - Q3; }
        else { s = Wg; d = g_wg; o = q - Q0 - Q1 - Q2 - Q3 - Q4; }
        float4 f = reinterpret_cast<const float4*>(s)[o];
        __nv_bfloat162 p0 = __floats2bfloat162_rn(f.x, f.y);
        __nv_bfloat162 p1 = __floats2bfloat162_rn(f.z, f.w);
        uint2 u;
        u.x = *reinterpret_cast<unsigned*>(&p0);
        u.y = *reinterpret_cast<unsigned*>(&p1);
        reinterpret_cast<uint2*>(d)[o] = u;
    }
}

__global__ void k_adj(const float* __restrict__ lw) {
    int i = threadIdx.x;
    if (i >= SEQL) return;
    float v[SEQL];
    float mx = -1e30f;
    #pragma unroll
    for (int j = 0; j < SEQL; j++) { v[j] = lw[i * SEQL + j]; mx = fmaxf(mx, v[j]); }
    float s = 0.f;
    #pragma unroll
    for (int j = 0; j < SEQL; j++) { v[j] = expf(v[j] - mx); s += v[j]; }
    float inv = 1.f / s;
    int any = 0;
    #pragma unroll
    for (int j = 0; j < SEQL; j++) {
        float a = v[j] * inv;
        int nb = (a > 0.01f);
        g_adj[i * SEQL + j] = nb ? a : 0.f;
        any |= nb;
    }
    g_hasnb[i] = any;
}

// ---------------- GEMM core pieces (128x128 tile, K-chunks of 64, cp.async 3-stage) ----
enum { EPI_F32 = 0, EPI_GELU = 1, EPI_MSG = 2 };

#define GEMM_PRELUDE                                                     \
    extern __shared__ __nv_bfloat16 smem[];                              \
    const int tid = threadIdx.x;                                         \
    const int lane = tid & 31;                                           \
    const int wid = tid >> 5;                                            \
    const int wm = wid >> 1;                                             \
    const int wn = wid & 1;                                              \
    const int bn = blockIdx.x;                                           \
    const int bm = blockIdx.y;                                           \
    unsigned sbase = (unsigned)__cvta_generic_to_shared(smem);           \
    unsigned aB = sbase;                                                 \
    unsigned bB = sbase + STAGES * A_ELEMS * 2;

// MMA compute over one 64-K stage
#define DEF_COMPUTE                                                                      \
    auto compute = [&](int st, float (&acc)[2][8][4]) {                                  \
        unsigned ab = aB + st * A_ELEMS * 2;                                             \
        unsigned bb = bB + st * B_ELEMS * 2;                                             \
        _Pragma("unroll")                                                                \
        for (int kk = 0; kk < 64; kk += 16) {                                            \
            unsigned a[2][4];                                                            \
            _Pragma("unroll")                                                            \
            for (int mi = 0; mi < 2; mi++) {                                             \
                int r = wm * 32 + mi * 16 + (lane & 15);                                 \
                int c = kk + ((lane >> 4) << 3);                                         \
                unsigned addr = ab + (unsigned)((r * ASTR + c) * 2);                     \
                asm volatile(                                                            \
                    "ldmatrix.sync.aligned.m8n8.x4.shared.b16 {%0,%1,%2,%3}, [%4];\n"    \
                    : "=r"(a[mi][0]), "=r"(a[mi][1]), "=r"(a[mi][2]), "=r"(a[mi][3])     \
                    : "r"(addr));                                                        \
            }                                                                            \
            unsigned b[4][4];                                                            \
            _Pragma("unroll")                                                            \
            for (int bi = 0; bi < 4; bi++) {                                             \
                int r = kk + (lane & 15);                                                \
                int c = wn * 64 + bi * 16 + ((lane >> 4) << 3);                          \
                unsigned addr = bb + (unsigned)((r * BSTR + c) * 2);                     \
                asm volatile(                                                            \
                    "ldmatrix.sync.aligned.m8n8.x4.trans.shared.b16 {%0,%1,%2,%3}, "     \
                    "[%4];\n"                                                            \
                    : "=r"(b[bi][0]), "=r"(b[bi][1]), "=r"(b[bi][2]), "=r"(b[bi][3])     \
                    : "r"(addr));                                                        \
            }                                                                            \
            _Pragma("unroll")                                                            \
            for (int mi = 0; mi < 2; mi++)                                               \
                _Pragma("unroll")                                                        \
                for (int ni = 0; ni < 8; ni++) {                                         \
                    unsigned b0 = b[ni >> 1][(ni & 1) * 2];                              \
                    unsigned b1 = b[ni >> 1][(ni & 1) * 2 + 1];                          \
                    asm volatile(                                                        \
                        "mma.sync.aligned.m16n8k16.row.col.f32.bf16.bf16.f32 "           \
                        "{%0,%1,%2,%3}, {%4,%5,%6,%7}, {%8,%9}, {%0,%1,%2,%3};\n"        \
                        : "+f"(acc[mi][ni][0]), "+f"(acc[mi][ni][1]),                    \
                          "+f"(acc[mi][ni][2]), "+f"(acc[mi][ni][3])                     \
                        : "r"(a[mi][0]), "r"(a[mi][1]), "r"(a[mi][2]), "r"(a[mi][3]),    \
                          "r"(b0), "r"(b1));                                             \
                }                                                                        \
        }                                                                                \
    };

// load one 64-K stage via cp.async; A optionally concatenated from two sources
#define DEF_LOADER                                                                       \
    auto load_stage = [&](int kt, int st, const __nv_bfloat16* A0,                       \
                          const __nv_bfloat16* A1, const __nv_bfloat16* W,               \
                          bool concat) {                                                 \
        unsigned ab = aB + st * A_ELEMS * 2;                                             \
        unsigned bb = bB + st * B_ELEMS * 2;                                             \
        _Pragma("unroll")                                                                \
        for (int i = 0; i < 4; i++) {                                                    \
            int v = tid + (i << 8);                                                      \
            int row = v >> 3;                                                            \
            int kc = (v & 7) << 3;                                                       \
            long grow = (long)bm * 128 + row;                                            \
            int gk = kt * 64 + kc;                                                       \
            const __nv_bfloat16* src = (concat && gk >= 512)                             \
                                           ? A1 + grow * 512 + (gk - 512)                \
                                           : A0 + grow * 512 + gk;                       \
            cp16(ab + (unsigned)((row * ASTR + kc) * 2), src);                           \
        }                                                                                \
        _Pragma("unroll")                                                                \
        for (int i = 0; i < 4; i++) {                                                    \
            int v = tid + (i << 8);                                                      \
            int row = v >> 4;                                                            \
            int nc = (v & 15) << 3;                                                      \
            cp16(bb + (unsigned)((row * BSTR + nc) * 2),                                 \
                 W + (long)(kt * 64 + row) * 512 + bn * 128 + nc);                       \
        }                                                                                \
        asm volatile("cp.async.commit_group;\n");                                        \
    };

#define RUN_PIPELINE(NK, A0, A1, W, CC, ACC)                                             \
    load_stage(0, 0, A0, A1, W, CC);                                                     \
    load_stage(1, 1, A0, A1, W, CC);                                                     \
    for (int kt = 0; kt < (NK); kt++) {                                                  \
        asm volatile("cp.async.wait_group 1;\n");                                        \
        __syncthreads();                                                                 \
        if (kt + 2 < (NK)) load_stage(kt + 2, (kt + 2) % STAGES, A0, A1, W, CC);         \
        compute(kt % STAGES, ACC);                                                       \
    }

// ---------------- standalone GEMM ----------------
template <int KTOT, bool CONCAT, int EPI>
__global__ void __launch_bounds__(256, 2) gemm_k(
    const __nv_bfloat16* __restrict__ A0, const __nv_bfloat16* __restrict__ A1,
    const __nv_bfloat16* __restrict__ W, const float* __restrict__ bias,
    void* __restrict__ outp)
{
    GEMM_PRELUDE
    DEF_COMPUTE
    DEF_LOADER
    float acc[2][8][4] = {};
    const int nk = KTOT / 64;
    RUN_PIPELINE(nk, A0, A1, W, CONCAT, acc)

    long rbase = (long)bm * 128 + wm * 32;
    int cbase = bn * 128 + wn * 64;
    #pragma unroll
    for (int mi = 0; mi < 2; mi++) {
        #pragma unroll
        for (int ni = 0; ni < 8; ni++) {
            int c0 = cbase + ni * 8 + (lane & 3) * 2;
            float bv0 = bias[c0], bv1 = bias[c0 + 1];
            long r0 = rbase + mi * 16 + (lane >> 2);
            long r1 = r0 + 8;
            float v00 = acc[mi][ni][0] + bv0;
            float v01 = acc[mi][ni][1] + bv1;
            float v10 = acc[mi][ni][2] + bv0;
            float v11 = acc[mi][ni][3] + bv1;
            if (EPI == EPI_F32) {
                float* o = (float*)outp;
                *reinterpret_cast<float2*>(o + r0 * 512 + c0) = make_float2(v00, v01);
                *reinterpret_cast<float2*>(o + r1 * 512 + c0) = make_float2(v10, v11);
            } else if (EPI == EPI_GELU) {
                __nv_bfloat16* o = (__nv_bfloat16*)outp;
                __nv_bfloat162 p0 = __floats2bfloat162_rn(geluf(v00), geluf(v01));
                __nv_bfloat162 p1 = __floats2bfloat162_rn(geluf(v10), geluf(v11));
                *reinterpret_cast<__nv_bfloat162*>(o + r0 * 512 + c0) = p0;
                *reinterpret_cast<__nv_bfloat162*>(o + r1 * 512 + c0) = p1;
            } else {  // EPI_MSG
                __nv_bfloat16* o = (__nv_bfloat16*)outp;
                int s0 = (int)(r0 % SEQL), s1 = (int)(r1 % SEQL);
                if (!g_hasnb[s0]) {
                    v00 = __bfloat162float(g_xt[r0 * 512 + c0]);
                    v01 = __bfloat162float(g_xt[r0 * 512 + c0 + 1]);
                }
                if (!g_hasnb[s1]) {
                    v10 = __bfloat162float(g_xt[r1 * 512 + c0]);
                    v11 = __bfloat162float(g_xt[r1 * 512 + c0 + 1]);
                }
                __nv_bfloat162 p0 = __floats2bfloat162_rn(v00, v01);
                __nv_bfloat162 p1 = __floats2bfloat162_rn(v10, v11);
                *reinterpret_cast<__nv_bfloat162*>(o + r0 * 512 + c0) = p0;
                *reinterpret_cast<__nv_bfloat162*>(o + r1 * 512 + c0) = p1;
            }
        }
    }
}

// ---------------- fused gate + Wo + sigmoid blend (writes final out) ----------------
__global__ void __launch_bounds__(256, 1) gemm_fused(
    const __nv_bfloat16* __restrict__ xbf, const __nv_bfloat16* __restrict__ msg,
    const __nv_bfloat16* __restrict__ Wg, const float* __restrict__ bg,
    const __nv_bfloat16* __restrict__ Wo, const float* __restrict__ bo,
    const float* __restrict__ x, float* __restrict__ out)
{
    GEMM_PRELUDE
    DEF_COMPUTE
    DEF_LOADER

    long rbase = (long)bm * 128 + wm * 32;
    int cbase = bn * 128 + wn * 64;

    // phase 1: gate logits over [xbf | msg] @ Wg, K=1024
    float accg[2][8][4] = {};
    RUN_PIPELINE(16, xbf, msg, Wg, true, accg)

    // g = sigmoid(logits + bg), in place
    #pragma unroll
    for (int mi = 0; mi < 2; mi++)
        #pragma unroll
        for (int ni = 0; ni < 8; ni++) {
            int c0 = cbase + ni * 8 + (lane & 3) * 2;
            float b0 = bg[c0], b1 = bg[c0 + 1];
            accg[mi][ni][0] = sigf(accg[mi][ni][0] + b0);
            accg[mi][ni][1] = sigf(accg[mi][ni][1] + b1);
            accg[mi][ni][2] = sigf(accg[mi][ni][2] + b0);
            accg[mi][ni][3] = sigf(accg[mi][ni][3] + b1);
        }

    asm volatile("cp.async.wait_group 0;\n");
    __syncthreads();

    // phase 2: mo = msg @ Wo, K=512
    float acco[2][8][4] = {};
    RUN_PIPELINE(8, msg, msg, Wo, false, acco)

    // out = g*(mo+bo) + (1-g)*x
    #pragma unroll
    for (int mi = 0; mi < 2; mi++) {
        #pragma unroll
        for (int ni = 0; ni < 8; ni++) {
            int c0 = cbase + ni * 8 + (lane & 3) * 2;
            float b0 = bo[c0], b1 = bo[c0 + 1];
            long r0 = rbase + mi * 16 + (lane >> 2);
            long r1 = r0 + 8;
            float2 x0 = *reinterpret_cast<const float2*>(x + r0 * 512 + c0);
            float2 x1 = *reinterpret_cast<const float2*>(x + r1 * 512 + c0);
            float g00 = accg[mi][ni][0], g01 = accg[mi][ni][1];
            float g10 = accg[mi][ni][2], g11 = accg[mi][ni][3];
            float2 o0, o1;
            o0.x = g00 * (acco[mi][ni][0] + b0) + (1.f - g00) * x0.x;
            o0.y = g01 * (acco[mi][ni][1] + b1) + (1.f - g01) * x0.y;
            o1.x = g10 * (acco[mi][ni][2] + b0) + (1.f - g10) * x1.x;
            o1.y = g11 * (acco[mi][ni][3] + b1) + (1.f - g11) * x1.y;
            *reinterpret_cast<float2*>(out + r0 * 512 + c0) = o0;
            *reinterpret_cast<float2*>(out + r1 * 512 + c0) = o1;
        }
    }
}

// ---------------- LN + gelu (one warp per row) ----------------
__global__ void __launch_bounds__(256) k_ln(const float* __restrict__ h,
                                            const float* __restrict__ lg,
                                            const float* __restrict__ lb) {
    long row = (long)blockIdx.x * 8 + (threadIdx.x >> 5);
    int lane = threadIdx.x & 31;
    const float* hr = h + row * 512;
    float v[16];
    float s = 0.f, s2 = 0.f;
    #pragma unroll
    for (int i = 0; i < 4; i++) {
        float4 f = *reinterpret_cast<const float4*>(hr + (i * 32 + lane) * 4);
        v[i * 4 + 0] = f.x; v[i * 4 + 1] = f.y; v[i * 4 + 2] = f.z; v[i * 4 + 3] = f.w;
        s += f.x + f.y + f.z + f.w;
        s2 += f.x * f.x + f.y * f.y + f.z * f.z + f.w * f.w;
    }
    #pragma unroll
    for (int o = 16; o > 0; o >>= 1) {
        s += __shfl_xor_sync(0xffffffffu, s, o);
        s2 += __shfl_xor_sync(0xffffffffu, s2, o);
    }
    float mu = s * (1.f / 512.f);
    float var = s2 * (1.f / 512.f) - mu * mu;
    float rstd = rsqrtf(var + 1e-5f);
    __nv_bfloat16* o = g_xt + row * 512;
    #pragma unroll
    for (int i = 0; i < 4; i++) {
        int c = (i * 32 + lane) * 4;
        float4 gv = *reinterpret_cast<const float4*>(lg + c);
        float4 bv = *reinterpret_cast<const float4*>(lb + c);
        float y0 = geluf((v[i * 4 + 0] - mu) * rstd * gv.x + bv.x);
        float y1 = geluf((v[i * 4 + 1] - mu) * rstd * gv.y + bv.y);
        float y2 = geluf((v[i * 4 + 2] - mu) * rstd * gv.z + bv.z);
        float y3 = geluf((v[i * 4 + 3] - mu) * rstd * gv.w + bv.w);
        __nv_bfloat162 p0 = __floats2bfloat162_rn(y0, y1);
        __nv_bfloat162 p1 = __floats2bfloat162_rn(y2, y3);
        uint2 u;
        u.x = *reinterpret_cast<unsigned*>(&p0);
        u.y = *reinterpret_cast<unsigned*>(&p1);
        *reinterpret_cast<uint2*>(o + c) = u;
    }
}

// ---------------- weighted = masked_adj @ x_t ----------------
__global__ void __launch_bounds__(256) k_weighted() {
    int b = blockIdx.x;
    int dc = blockIdx.y;
    __shared__ float sadj[SEQL * SEQL];
    __shared__ __align__(16) __nv_bfloat16 sx[SEQL][128];
    int tid = threadIdx.x;
    for (int i = tid; i < SEQL * SEQL; i += 256) sadj[i] = g_adj[i];
    #pragma unroll
    for (int i = 0; i < 3; i++) {
        int v = tid + i * 256;
        int j = v >> 4;
        int n = (v & 15) << 3;
        *reinterpret_cast<uint4*>(&sx[j][n]) =
            *reinterpret_cast<const uint4*>(&g_xt[((long)b * SEQL + j) * 512 + dc * 128 + n]);
    }
    __syncthreads();
    int dd = tid & 127;
    int half = tid >> 7;
    float xcol[SEQL];
    #pragma unroll
    for (int j = 0; j < SEQL; j++) xcol[j] = __bfloat162float(sx[j][dd]);
    for (int ii = 0; ii < 24; ii++) {
        int i = half * 24 + ii;
        float a = 0.f;
        #pragma unroll
        for (int j = 0; j < SEQL; j++) a += sadj[i * SEQL + j] * xcol[j];
        g_wt[((long)b * SEQL + i) * 512 + dc * 128 + dd] = __float2bfloat16(a);
    }
}

// ---------------- launch ----------------
extern "C" void kernel_launch(void* const* d_in, const int* in_sizes, int n_in,
                              void* d_out, int out_size) {
    const float* x = (const float*)d_in[0];
    const float* lw = (const float*)d_in[1];
    const float* Wnt = (const float*)d_in[2];
    const float* bnt = (const float*)d_in[3];
    const float* lng = (const float*)d_in[4];
    const float* lnb = (const float*)d_in[5];
    const float* We1 = (const float*)d_in[6];
    const float* be1 = (const float*)d_in[7];
    const float* We2 = (const float*)d_in[8];
    const float* be2 = (const float*)d_in[9];
    const float* Wo = (const float*)d_in[10];
    const float* bo = (const float*)d_in[11];
    const float* Wg = (const float*)d_in[12];
    const float* bg = (const float*)d_in[13];
    float* out = (float*)d_out;

    void *p_wnt, *p_we1, *p_we2, *p_wo, *p_wg, *p_xbf, *p_xt, *p_wt, *p_h1, *p_msg, *p_h;
    cudaGetSymbolAddress(&p_wnt, g_wnt);
    cudaGetSymbolAddress(&p_we1, g_we1);
    cudaGetSymbolAddress(&p_we2, g_we2);
    cudaGetSymbolAddress(&p_wo, g_wo);
    cudaGetSymbolAddress(&p_wg, g_wg);
    cudaGetSymbolAddress(&p_xbf, g_xbf);
    cudaGetSymbolAddress(&p_xt, g_xt);
    cudaGetSymbolAddress(&p_wt, g_wt);
    cudaGetSymbolAddress(&p_h1, g_h1);
    cudaGetSymbolAddress(&p_msg, g_msg);
    cudaGetSymbolAddress(&p_h, g_h);

    static bool attr_done = false;
    if (!attr_done) {
        cudaFuncSetAttribute(gemm_k<512, false, EPI_F32>,
                             cudaFuncAttributeMaxDynamicSharedMemorySize, SMEM_BYTES);
        cudaFuncSetAttribute(gemm_k<1024, true, EPI_GELU>,
                             cudaFuncAttributeMaxDynamicSharedMemorySize, SMEM_BYTES);
        cudaFuncSetAttribute(gemm_k<512, false, EPI_MSG>,
                             cudaFuncAttributeMaxDynamicSharedMemorySize, SMEM_BYTES);
        cudaFuncSetAttribute(gemm_fused,
                             cudaFuncAttributeMaxDynamicSharedMemorySize, SMEM_BYTES);
        attr_done = true;
    }

    dim3 gg(4, MROWS / 128);  // bn fast, bm slow -> A-tile L2 reuse across bn

    // 1) convert x + weights to bf16
    k_prep<<<4096, 256>>>(x, Wnt, We1, We2, Wo, Wg);
    // 2) adjacency
    k_adj<<<1, 64>>>(lw);
    // 3) h = x @ Wnt + bnt (fp32)
    gemm_k<512, false, EPI_F32><<<gg, 256, SMEM_BYTES>>>(
        (const __nv_bfloat16*)p_xbf, nullptr, (__nv_bfloat16*)p_wnt, bnt, p_h);
    // 4) x_t = gelu(LN(h))
    k_ln<<<MROWS / 8, 256>>>((const float*)p_h, lng, lnb);
    // 5) weighted = masked_adj @ x_t
    k_weighted<<<dim3(4096, 4), 256>>>();
    // 6) h1 = gelu([x_t|weighted] @ We1 + be1)   <- ncu -s 5 -c 1 captures this
    gemm_k<1024, true, EPI_GELU><<<gg, 256, SMEM_BYTES>>>(
        (const __nv_bfloat16*)p_xt, (const __nv_bfloat16*)p_wt,
        (__nv_bfloat16*)p_we1, be1, p_h1);
    // 7) messages = blend(h1 @ We2 + be2, x_t)
    gemm_k<512, false, EPI_MSG><<<gg, 256, SMEM_BYTES>>>(
        (const __nv_bfloat16*)p_h1, nullptr, (__nv_bfloat16*)p_we2, be2, p_msg);
    // 8) fused: g = sigmoid([x|msg]@Wg+bg); out = g*(msg@Wo+bo) + (1-g)*x
    gemm_fused<<<gg, 256, SMEM_BYTES>>>(
        (const __nv_bfloat16*)p_xbf, (const __nv_bfloat16*)p_msg,
        (__nv_bfloat16*)p_wg, bg, (__nv_bfloat16*)p_wo, bo, x, out);
}